// round 4
// baseline (speedup 1.0000x reference)
#include <cuda_runtime.h>
#include <math.h>

#define N_NODES 100000
#define N_EDGES 3200000
#define DH1 512
#define DH2 256
#define KCLUST 64
#define NUM_ITER 10

// ---------------- f32x2 packed helpers (Blackwell sm_100+) ----------------
__device__ __forceinline__ unsigned long long pack2(float lo, float hi) {
    unsigned long long r;
    asm("mov.b64 %0, {%1, %2};" : "=l"(r) : "f"(lo), "f"(hi));
    return r;
}
__device__ __forceinline__ void unpack2(unsigned long long v, float& lo, float& hi) {
    asm("mov.b64 {%0, %1}, %2;" : "=f"(lo), "=f"(hi) : "l"(v));
}
__device__ __forceinline__ unsigned long long fma2(unsigned long long a,
                                                   unsigned long long b,
                                                   unsigned long long c) {
    unsigned long long d;
    asm("fma.rn.f32x2 %0, %1, %2, %3;" : "=l"(d) : "l"(a), "l"(b), "l"(c));
    return d;
}

// ---------------- scratch (device globals; no allocation allowed) ----------------
__device__ float g_Y1[(size_t)N_NODES * DH1];    // x @ W1
__device__ float g_H [(size_t)N_NODES * DH1];    // spmm(Y1) + b1
__device__ float g_Y2[(size_t)N_NODES * DH2];    // H @ W2
__device__ float g_data[(size_t)N_NODES * DH2];  // row-normalized embeds
__device__ int   g_rowptr[N_NODES + 1];
__device__ int   g_wptr  [N_NODES + 1];
__device__ int2  g_srcw[N_EDGES];                // (src, w-bits) grouped by dst
__device__ float g_mu[KCLUST * DH2];
__device__ float g_cmean[KCLUST * DH2];
__device__ float g_cr[KCLUST];

// ---------------- small utility kernels ----------------
__global__ void zero_int_k(int* p, int n) {
    int t = blockIdx.x * blockDim.x + threadIdx.x;
    if (t < n) p[t] = 0;
}
__global__ void copy_int_k(const int* s, int* d, int n) {
    int t = blockIdx.x * blockDim.x + threadIdx.x;
    if (t < n) d[t] = s[t];
}
__global__ void copy_f_k(const float* s, float* d, int n) {
    int t = blockIdx.x * blockDim.x + threadIdx.x;
    if (t < n) d[t] = s[t];
}
__global__ void zero_accum_k() {
    int t = blockIdx.x * blockDim.x + threadIdx.x;
    if (t < KCLUST * DH2) g_cmean[t] = 0.0f;
    if (t < KCLUST) g_cr[t] = 0.0f;
}
__global__ void mu_update_k() {
    int t = blockIdx.x * blockDim.x + threadIdx.x;
    if (t < KCLUST * DH2) g_mu[t] = g_cmean[t] / g_cr[t >> 8];
}

// ---------------- CSR build ----------------
__global__ void hist_k(const int* __restrict__ dst, int* __restrict__ counts, int E) {
    int e = blockIdx.x * blockDim.x + threadIdx.x;
    if (e < E) atomicAdd(&counts[dst[e]], 1);
}

__global__ void scan_block_k(const int* __restrict__ counts, int* __restrict__ rowptr, int n) {
    __shared__ int ssum[1024];
    int tid = threadIdx.x;
    int chunk = (n + 1023) >> 10;
    int beg = tid * chunk;
    int end = min(beg + chunk, n);
    int s = 0;
    for (int i = beg; i < end; i++) s += counts[i];
    ssum[tid] = s;
    __syncthreads();
    for (int off = 1; off < 1024; off <<= 1) {
        int v = (tid >= off) ? ssum[tid - off] : 0;
        __syncthreads();
        ssum[tid] += v;
        __syncthreads();
    }
    int run = (tid > 0) ? ssum[tid - 1] : 0;
    for (int i = beg; i < end; i++) { rowptr[i] = run; run += counts[i]; }
    if (tid == 0) rowptr[n] = ssum[1023];
}

__global__ void scatter_k(const int* __restrict__ src, const int* __restrict__ dst,
                          const float* __restrict__ w, int* __restrict__ wptr,
                          int2* __restrict__ srcw, int E) {
    int e = blockIdx.x * blockDim.x + threadIdx.x;
    if (e < E) {
        int p = atomicAdd(&wptr[dst[e]], 1);
        srcw[p] = make_int2(src[e], __float_as_int(w[e]));
    }
}

// ---------------- SpMM via CSR: out[d] = sum_e w_e * Yin[src_e] + bias ----------------
template <int D>
__global__ void spmm_csr_k(const float* __restrict__ Yin, float* __restrict__ out,
                           const float* __restrict__ bias) {
    constexpr int T = D / 4;
    __shared__ int2 meta[T];
    int d = blockIdx.x;
    int tid = threadIdx.x;
    int s0 = g_rowptr[d], s1 = g_rowptr[d + 1];
    float4 acc = make_float4(0.f, 0.f, 0.f, 0.f);
    for (int base = s0; base < s1; base += T) {
        int cnt = min(T, s1 - base);
        __syncthreads();
        if (tid < cnt) meta[tid] = g_srcw[base + tid];
        __syncthreads();
        int i = 0;
        for (; i + 4 <= cnt; i += 4) {
            int2 m0 = meta[i], m1 = meta[i + 1], m2 = meta[i + 2], m3 = meta[i + 3];
            float4 v0 = *(const float4*)(Yin + (size_t)m0.x * D + tid * 4);
            float4 v1 = *(const float4*)(Yin + (size_t)m1.x * D + tid * 4);
            float4 v2 = *(const float4*)(Yin + (size_t)m2.x * D + tid * 4);
            float4 v3 = *(const float4*)(Yin + (size_t)m3.x * D + tid * 4);
            float w0 = __int_as_float(m0.y), w1 = __int_as_float(m1.y);
            float w2 = __int_as_float(m2.y), w3 = __int_as_float(m3.y);
            acc.x += w0 * v0.x; acc.y += w0 * v0.y; acc.z += w0 * v0.z; acc.w += w0 * v0.w;
            acc.x += w1 * v1.x; acc.y += w1 * v1.y; acc.z += w1 * v1.z; acc.w += w1 * v1.w;
            acc.x += w2 * v2.x; acc.y += w2 * v2.y; acc.z += w2 * v2.z; acc.w += w2 * v2.w;
            acc.x += w3 * v3.x; acc.y += w3 * v3.y; acc.z += w3 * v3.z; acc.w += w3 * v3.w;
        }
        for (; i < cnt; i++) {
            int2 m = meta[i];
            float4 v = *(const float4*)(Yin + (size_t)m.x * D + tid * 4);
            float w = __int_as_float(m.y);
            acc.x += w * v.x; acc.y += w * v.y; acc.z += w * v.z; acc.w += w * v.w;
        }
    }
    float4 b = *(const float4*)(bias + tid * 4);
    acc.x += b.x; acc.y += b.y; acc.z += b.z; acc.w += b.w;
    *(float4*)(out + (size_t)d * D + tid * 4) = acc;
}

// ---------------- SGEMM: C[M,N] = A[M,K] @ B[K,N], row-major, fp32 ----------------
// 128x128 tile, BK=16, 256 threads, 8x8 micro (f32x2), double-buffered + reg prefetch
__global__ __launch_bounds__(256) void sgemm128_k(const float* __restrict__ A,
                                                  const float* __restrict__ B,
                                                  float* __restrict__ C,
                                                  int M, int N, int K) {
    __shared__ float As[2][16][132];
    __shared__ float Bs[2][16][128];
    int tid = threadIdx.x;
    int m0 = (tid & 15) * 8;
    int n0 = (tid >> 4) * 8;
    int blockM = blockIdx.x * 128;
    int blockN = blockIdx.y * 128;

    int aM[2], aKq[2], bKr[2], bNq[2];
    bool aOk[2];
    #pragma unroll
    for (int l = 0; l < 2; l++) {
        int lin = tid + l * 256;
        aM[l] = lin >> 2;
        aKq[l] = (lin & 3) * 4;
        aOk[l] = (blockM + aM[l]) < M;
        bKr[l] = lin >> 5;
        bNq[l] = (lin & 31) * 4;
    }

    unsigned long long accp[8][4];
    #pragma unroll
    for (int i = 0; i < 8; i++)
        #pragma unroll
        for (int j = 0; j < 4; j++) accp[i][j] = 0ull;

    const int KT = K >> 4;
    {
        #pragma unroll
        for (int l = 0; l < 2; l++) {
            float4 v = make_float4(0.f, 0.f, 0.f, 0.f);
            if (aOk[l]) v = *(const float4*)(A + (size_t)(blockM + aM[l]) * K + aKq[l]);
            As[0][aKq[l] + 0][aM[l]] = v.x; As[0][aKq[l] + 1][aM[l]] = v.y;
            As[0][aKq[l] + 2][aM[l]] = v.z; As[0][aKq[l] + 3][aM[l]] = v.w;
            float4 u = *(const float4*)(B + (size_t)bKr[l] * N + blockN + bNq[l]);
            *(float4*)&Bs[0][bKr[l]][bNq[l]] = u;
        }
    }
    __syncthreads();

    for (int kt = 0; kt < KT; kt++) {
        int buf = kt & 1;
        float4 pa[2], pb[2];
        bool more = (kt + 1) < KT;
        if (more) {
            int k0 = (kt + 1) << 4;
            #pragma unroll
            for (int l = 0; l < 2; l++) {
                pa[l] = make_float4(0.f, 0.f, 0.f, 0.f);
                if (aOk[l]) pa[l] = *(const float4*)(A + (size_t)(blockM + aM[l]) * K + k0 + aKq[l]);
                pb[l] = *(const float4*)(B + (size_t)(k0 + bKr[l]) * N + blockN + bNq[l]);
            }
        }
        #pragma unroll
        for (int k = 0; k < 16; k++) {
            float4 a0 = *(const float4*)&As[buf][k][m0];
            float4 a1 = *(const float4*)&As[buf][k][m0 + 4];
            float4 b0 = *(const float4*)&Bs[buf][k][n0];
            float4 b1 = *(const float4*)&Bs[buf][k][n0 + 4];
            unsigned long long bp[4];
            bp[0] = pack2(b0.x, b0.y); bp[1] = pack2(b0.z, b0.w);
            bp[2] = pack2(b1.x, b1.y); bp[3] = pack2(b1.z, b1.w);
            float av[8] = {a0.x, a0.y, a0.z, a0.w, a1.x, a1.y, a1.z, a1.w};
            #pragma unroll
            for (int i = 0; i < 8; i++) {
                unsigned long long ap = pack2(av[i], av[i]);
                #pragma unroll
                for (int j = 0; j < 4; j++) accp[i][j] = fma2(ap, bp[j], accp[i][j]);
            }
        }
        if (more) {
            int nb = 1 - buf;
            #pragma unroll
            for (int l = 0; l < 2; l++) {
                As[nb][aKq[l] + 0][aM[l]] = pa[l].x; As[nb][aKq[l] + 1][aM[l]] = pa[l].y;
                As[nb][aKq[l] + 2][aM[l]] = pa[l].z; As[nb][aKq[l] + 3][aM[l]] = pa[l].w;
                *(float4*)&Bs[nb][bKr[l]][bNq[l]] = pb[l];
            }
        }
        __syncthreads();
    }

    #pragma unroll
    for (int i = 0; i < 8; i++) {
        int gm = blockM + m0 + i;
        if (gm < M) {
            float4 c0, c1;
            unpack2(accp[i][0], c0.x, c0.y); unpack2(accp[i][1], c0.z, c0.w);
            unpack2(accp[i][2], c1.x, c1.y); unpack2(accp[i][3], c1.z, c1.w);
            *(float4*)(C + (size_t)gm * N + blockN + n0) = c0;
            *(float4*)(C + (size_t)gm * N + blockN + n0 + 4) = c1;
        }
    }
}

// ---------------- row normalize ----------------
__global__ void normalize_rows_k(const float* __restrict__ E, float* __restrict__ out, int N) {
    int row = blockIdx.x * 8 + (threadIdx.x >> 5);
    int lane = threadIdx.x & 31;
    if (row >= N) return;
    const float* rp = E + (size_t)row * DH2;
    float4 v0 = *(const float4*)(rp + lane * 4);
    float4 v1 = *(const float4*)(rp + 128 + lane * 4);
    float s = v0.x * v0.x + v0.y * v0.y + v0.z * v0.z + v0.w * v0.w
            + v1.x * v1.x + v1.y * v1.y + v1.z * v1.z + v1.w * v1.w;
    #pragma unroll
    for (int o = 16; o > 0; o >>= 1) s += __shfl_xor_sync(0xffffffffu, s, o);
    float inv = 1.0f / sqrtf(s);
    float* op = out + (size_t)row * DH2;
    v0.x *= inv; v0.y *= inv; v0.z *= inv; v0.w *= inv;
    v1.x *= inv; v1.y *= inv; v1.z *= inv; v1.w *= inv;
    *(float4*)(op + lane * 4) = v0;
    *(float4*)(op + 128 + lane * 4) = v1;
}

// ---------------- FUSED k-means iteration ----------------
// Persistent: grid=296 blocks x 256 threads. Each block loops over 64-row tiles:
//   Phase A: dist = tile @ mu^T (mu streamed in 32-col chunks), softmax -> r in smem
//   Phase B: accumulate r^T @ tile into persistent register accumulators
// Flush accumulators (atomics) once per block at the end.
// Dynamic smem: sdata[64*260] | sdist[64*65] | smu[64*36]
#define FUSED_SMEM_FLOATS (64 * 260 + 64 * 65 + 64 * 36)
__global__ __launch_bounds__(256, 2) void kmeans_fused_k(const float* __restrict__ data) {
    extern __shared__ float smemf[];
    float* sdata = smemf;                 // [64][260]
    float* sdist = sdata + 64 * 260;      // [64][65] (dist, then r in-place)
    float* smu   = sdist + 64 * 65;       // [64][36]

    int tid = threadIdx.x;
    int mr = tid & 15;            // row lane: rows mr + 16*i
    int k0 = (tid >> 4) * 4;      // K group (16 groups x 4 = 64)
    int lane = tid & 31, warp = tid >> 5;

    // Phase-B persistent accumulators: thread owns K rows k0..k0+3,
    // D cols: {mr*4 + 64*cb + q : cb in 0..3, q in 0..3}
    unsigned long long accB[4][8];
    #pragma unroll
    for (int i = 0; i < 4; i++)
        #pragma unroll
        for (int c = 0; c < 8; c++) accB[i][c] = 0ull;
    float accR[4] = {0.f, 0.f, 0.f, 0.f};

    const int nTiles = (N_NODES + 63) >> 6;
    for (int t = blockIdx.x; t < nTiles; t += gridDim.x) {
        int tileBase = t << 6;
        __syncthreads();   // previous tile's Phase B done before overwriting sdata/sdist

        // load 64x256 data tile
        #pragma unroll
        for (int l = 0; l < 16; l++) {
            int lin = tid + l * 256;      // 4096 float4
            int row = lin >> 6;
            int q = (lin & 63) * 4;
            int gr = tileBase + row;
            float4 v = make_float4(0.f, 0.f, 0.f, 0.f);
            if (gr < N_NODES) v = *(const float4*)(data + (size_t)gr * DH2 + q);
            *(float4*)&sdata[row * 260 + q] = v;
        }

        // Phase A: dist
        unsigned long long accA[4][2];
        #pragma unroll
        for (int i = 0; i < 4; i++) { accA[i][0] = 0ull; accA[i][1] = 0ull; }

        for (int kk = 0; kk < DH2; kk += 32) {
            __syncthreads();   // covers sdata stores (first iter) + smu reuse
            #pragma unroll
            for (int l = 0; l < 2; l++) {
                int lin = tid + l * 256;   // 512 float4 = 64x32
                int row = lin >> 3;
                int q = (lin & 7) * 4;
                *(float4*)&smu[row * 36 + q] = *(const float4*)(g_mu + row * DH2 + kk + q);
            }
            __syncthreads();
            #pragma unroll
            for (int j = 0; j < 32; j += 4) {
                float4 a4[4], b4[4];
                #pragma unroll
                for (int i = 0; i < 4; i++) a4[i] = *(const float4*)&sdata[(mr + 16 * i) * 260 + kk + j];
                #pragma unroll
                for (int c = 0; c < 4; c++) b4[c] = *(const float4*)&smu[(k0 + c) * 36 + j];
                const float* af = (const float*)a4;
                const float* bf = (const float*)b4;
                #pragma unroll
                for (int jj = 0; jj < 4; jj++) {
                    unsigned long long bp0 = pack2(bf[0 * 4 + jj], bf[1 * 4 + jj]);
                    unsigned long long bp1 = pack2(bf[2 * 4 + jj], bf[3 * 4 + jj]);
                    #pragma unroll
                    for (int i = 0; i < 4; i++) {
                        float a = af[i * 4 + jj];
                        unsigned long long ap = pack2(a, a);
                        accA[i][0] = fma2(ap, bp0, accA[i][0]);
                        accA[i][1] = fma2(ap, bp1, accA[i][1]);
                    }
                }
            }
        }
        #pragma unroll
        for (int i = 0; i < 4; i++) {
            float c0, c1, c2, c3;
            unpack2(accA[i][0], c0, c1);
            unpack2(accA[i][1], c2, c3);
            float* dp = &sdist[(mr + 16 * i) * 65 + k0];
            dp[0] = c0; dp[1] = c1; dp[2] = c2; dp[3] = c3;
        }
        __syncthreads();

        // softmax (in place: dist -> r), zero rows beyond N
        for (int rr = warp; rr < 64; rr += 8) {
            float v0 = sdist[rr * 65 + lane];
            float v1 = sdist[rr * 65 + 32 + lane];
            float mx = fmaxf(v0, v1);
            #pragma unroll
            for (int o = 16; o > 0; o >>= 1) mx = fmaxf(mx, __shfl_xor_sync(0xffffffffu, mx, o));
            float e0 = expf(30.0f * (v0 - mx));
            float e1 = expf(30.0f * (v1 - mx));
            float s = e0 + e1;
            #pragma unroll
            for (int o = 16; o > 0; o >>= 1) s += __shfl_xor_sync(0xffffffffu, s, o);
            float inv = 1.0f / s;
            bool ok = (tileBase + rr) < N_NODES;
            sdist[rr * 65 + lane] = ok ? e0 * inv : 0.0f;
            sdist[rr * 65 + 32 + lane] = ok ? e1 * inv : 0.0f;
        }
        __syncthreads();

        // Phase B: accumulate r^T @ data over 64 rows
        #pragma unroll 4
        for (int rit = 0; rit < 64; rit++) {
            int row = (rit + k0) & 63;   // stagger
            float rv[4];
            unsigned long long rvp[4];
            #pragma unroll
            for (int i = 0; i < 4; i++) {
                rv[i] = sdist[row * 65 + k0 + i];
                rvp[i] = pack2(rv[i], rv[i]);
            }
            #pragma unroll
            for (int cb = 0; cb < 4; cb++) {
                float4 dv = *(const float4*)&sdata[row * 260 + mr * 4 + 64 * cb];
                unsigned long long dp0 = pack2(dv.x, dv.y);
                unsigned long long dp1 = pack2(dv.z, dv.w);
                #pragma unroll
                for (int i = 0; i < 4; i++) {
                    accB[i][cb * 2 + 0] = fma2(rvp[i], dp0, accB[i][cb * 2 + 0]);
                    accB[i][cb * 2 + 1] = fma2(rvp[i], dp1, accB[i][cb * 2 + 1]);
                }
            }
            if (mr == 0) {
                #pragma unroll
                for (int i = 0; i < 4; i++) accR[i] += rv[i];
            }
        }
    }

    // flush
    #pragma unroll
    for (int i = 0; i < 4; i++)
        #pragma unroll
        for (int cb = 0; cb < 4; cb++) {
            int bd = mr * 4 + 64 * cb;
            float lo, hi;
            unpack2(accB[i][cb * 2 + 0], lo, hi);
            atomicAdd(&g_cmean[(k0 + i) * DH2 + bd + 0], lo);
            atomicAdd(&g_cmean[(k0 + i) * DH2 + bd + 1], hi);
            unpack2(accB[i][cb * 2 + 1], lo, hi);
            atomicAdd(&g_cmean[(k0 + i) * DH2 + bd + 2], lo);
            atomicAdd(&g_cmean[(k0 + i) * DH2 + bd + 3], hi);
        }
    if (mr == 0) {
        #pragma unroll
        for (int i = 0; i < 4; i++) atomicAdd(&g_cr[k0 + i], accR[i]);
    }
}

// ---------------- final assign: writes r and dist to output ----------------
__global__ __launch_bounds__(256) void kmeans_assign_k(const float* __restrict__ data,
                                                       float* __restrict__ r_out,
                                                       float* __restrict__ dist_out) {
    __shared__ float sdata[64 * 36];
    __shared__ float smu[64 * 36];
    __shared__ float sdist[64 * 65];
    int tid = threadIdx.x;
    int rowBase = blockIdx.x * 64;
    int m0 = (tid & 15) * 4;
    int k0 = (tid >> 4) * 4;
    unsigned long long accp[4][2];
    #pragma unroll
    for (int i = 0; i < 4; i++) { accp[i][0] = 0ull; accp[i][1] = 0ull; }

    for (int kk = 0; kk < DH2; kk += 32) {
        #pragma unroll
        for (int l = 0; l < 2; l++) {
            int lin = tid + l * 256;
            int row = lin >> 3;
            int q = (lin & 7) * 4;
            int gr = rowBase + row;
            float4 v = make_float4(0.f, 0.f, 0.f, 0.f);
            if (gr < N_NODES) v = *(const float4*)(data + (size_t)gr * DH2 + kk + q);
            *(float4*)&sdata[row * 36 + q] = v;
            float4 u = *(const float4*)(g_mu + row * DH2 + kk + q);
            *(float4*)&smu[row * 36 + q] = u;
        }
        __syncthreads();
        #pragma unroll
        for (int j = 0; j < 32; j += 4) {
            float4 a4[4], b4[4];
            #pragma unroll
            for (int i = 0; i < 4; i++) a4[i] = *(const float4*)&sdata[(m0 + i) * 36 + j];
            #pragma unroll
            for (int c = 0; c < 4; c++) b4[c] = *(const float4*)&smu[(k0 + c) * 36 + j];
            const float* af = (const float*)a4;
            const float* bf = (const float*)b4;
            #pragma unroll
            for (int jj = 0; jj < 4; jj++) {
                unsigned long long bp0 = pack2(bf[0 * 4 + jj], bf[1 * 4 + jj]);
                unsigned long long bp1 = pack2(bf[2 * 4 + jj], bf[3 * 4 + jj]);
                #pragma unroll
                for (int i = 0; i < 4; i++) {
                    float a = af[i * 4 + jj];
                    unsigned long long ap = pack2(a, a);
                    accp[i][0] = fma2(ap, bp0, accp[i][0]);
                    accp[i][1] = fma2(ap, bp1, accp[i][1]);
                }
            }
        }
        __syncthreads();
    }
    #pragma unroll
    for (int i = 0; i < 4; i++) {
        float c0, c1, c2, c3;
        unpack2(accp[i][0], c0, c1);
        unpack2(accp[i][1], c2, c3);
        float* dp = &sdist[(m0 + i) * 65 + k0];
        dp[0] = c0; dp[1] = c1; dp[2] = c2; dp[3] = c3;
    }
    __syncthreads();

    int lane = tid & 31, warp = tid >> 5;
    for (int rr = warp; rr < 64; rr += 8) {
        float v0 = sdist[rr * 65 + lane];
        float v1 = sdist[rr * 65 + 32 + lane];
        float mx = fmaxf(v0, v1);
        #pragma unroll
        for (int o = 16; o > 0; o >>= 1) mx = fmaxf(mx, __shfl_xor_sync(0xffffffffu, mx, o));
        float e0 = expf(30.0f * (v0 - mx));
        float e1 = expf(30.0f * (v1 - mx));
        float s = e0 + e1;
        #pragma unroll
        for (int o = 16; o > 0; o >>= 1) s += __shfl_xor_sync(0xffffffffu, s, o);
        float inv = 1.0f / s;
        int gr = rowBase + rr;
        if (gr < N_NODES) {
            r_out[(size_t)gr * KCLUST + lane] = e0 * inv;
            r_out[(size_t)gr * KCLUST + 32 + lane] = e1 * inv;
            dist_out[(size_t)gr * KCLUST + lane] = v0;
            dist_out[(size_t)gr * KCLUST + 32 + lane] = v1;
        }
    }
}

// ---------------- host ----------------
extern "C" void kernel_launch(void* const* d_in, const int* in_sizes, int n_in,
                              void* d_out, int out_size) {
    const float* x    = (const float*)d_in[0];
    const int*   esrc = (const int*)d_in[1];
    const int*   edst = (const int*)d_in[2];
    const float* ew   = (const float*)d_in[3];
    const float* W1   = (const float*)d_in[4];
    const float* b1   = (const float*)d_in[5];
    const float* W2   = (const float*)d_in[6];
    const float* b2   = (const float*)d_in[7];
    const float* mu0  = (const float*)d_in[8];
    (void)in_sizes; (void)n_in; (void)out_size;

    float* out      = (float*)d_out;
    float* out_mu   = out;                                   // [64,256]
    float* out_r    = out_mu + KCLUST * DH2;                 // [N,64]
    float* out_emb  = out_r + (size_t)N_NODES * KCLUST;      // [N,256]
    float* out_dist = out_emb + (size_t)N_NODES * DH2;       // [N,64]

    float *pY1, *pH, *pY2, *pdata, *pmu;
    int *prow, *pwp; int2* psrcw;
    cudaGetSymbolAddress((void**)&pY1, g_Y1);
    cudaGetSymbolAddress((void**)&pH, g_H);
    cudaGetSymbolAddress((void**)&pY2, g_Y2);
    cudaGetSymbolAddress((void**)&pdata, g_data);
    cudaGetSymbolAddress((void**)&pmu, g_mu);
    cudaGetSymbolAddress((void**)&prow, g_rowptr);
    cudaGetSymbolAddress((void**)&pwp, g_wptr);
    cudaGetSymbolAddress((void**)&psrcw, g_srcw);

    // opt-in to >48KB dynamic smem for fused kernel (idempotent)
    static const int FUSED_SMEM_BYTES = FUSED_SMEM_FLOATS * 4;
    cudaFuncSetAttribute(kmeans_fused_k, cudaFuncAttributeMaxDynamicSharedMemorySize,
                         FUSED_SMEM_BYTES);

    // --- CSR build (by dst) ---
    zero_int_k<<<(N_NODES + 255) / 256, 256>>>(pwp, N_NODES);
    hist_k<<<(N_EDGES + 255) / 256, 256>>>(edst, pwp, N_EDGES);
    scan_block_k<<<1, 1024>>>(pwp, prow, N_NODES);
    copy_int_k<<<(N_NODES + 255) / 256, 256>>>(prow, pwp, N_NODES);
    scatter_k<<<(N_EDGES + 255) / 256, 256>>>(esrc, edst, ew, pwp, psrcw, N_EDGES);

    // --- GCN forward ---
    sgemm128_k<<<dim3((N_NODES + 127) / 128, DH1 / 128), 256>>>(x, W1, pY1, N_NODES, DH1, DH1);
    spmm_csr_k<DH1><<<N_NODES, DH1 / 4>>>(pY1, pH, b1);
    sgemm128_k<<<dim3((N_NODES + 127) / 128, DH2 / 128), 256>>>(pH, W2, pY2, N_NODES, DH2, DH1);
    spmm_csr_k<DH2><<<N_NODES, DH2 / 4>>>(pY2, out_emb, b2);

    // --- normalize + k-means ---
    normalize_rows_k<<<(N_NODES + 7) / 8, 256>>>(out_emb, pdata, N_NODES);
    copy_f_k<<<(KCLUST * DH2 + 255) / 256, 256>>>(mu0, pmu, KCLUST * DH2);

    for (int it = 0; it < NUM_ITER; it++) {
        zero_accum_k<<<(KCLUST * DH2 + 255) / 256, 256>>>();
        kmeans_fused_k<<<296, 256, FUSED_SMEM_BYTES>>>(pdata);
        mu_update_k<<<(KCLUST * DH2 + 255) / 256, 256>>>();
    }
    // final assign with converged mu: writes r and dist to output
    kmeans_assign_k<<<(N_NODES + 63) / 64, 256>>>(pdata, out_r, out_dist);
    copy_f_k<<<(KCLUST * DH2 + 255) / 256, 256>>>(pmu, out_mu, KCLUST * DH2);
}

// round 5
// speedup vs baseline: 1.4531x; 1.4531x over previous
#include <cuda_runtime.h>
#include <math.h>

#define N_NODES 100000
#define N_EDGES 3200000
#define DH1 512
#define DH2 256
#define KCLUST 64
#define NUM_ITER 10

// ---------------- f32x2 packed helpers (Blackwell sm_100+) ----------------
__device__ __forceinline__ unsigned long long pack2(float lo, float hi) {
    unsigned long long r;
    asm("mov.b64 %0, {%1, %2};" : "=l"(r) : "f"(lo), "f"(hi));
    return r;
}
__device__ __forceinline__ void unpack2(unsigned long long v, float& lo, float& hi) {
    asm("mov.b64 {%0, %1}, %2;" : "=f"(lo), "=f"(hi) : "l"(v));
}
__device__ __forceinline__ unsigned long long fma2(unsigned long long a,
                                                   unsigned long long b,
                                                   unsigned long long c) {
    unsigned long long d;
    asm("fma.rn.f32x2 %0, %1, %2, %3;" : "=l"(d) : "l"(a), "l"(b), "l"(c));
    return d;
}

// ---------------- scratch (device globals; no allocation allowed) ----------------
__device__ float g_W12[DH1 * DH2];               // W1 @ W2
__device__ float g_c1[DH2];                      // b1 @ W2
__device__ float g_Y [(size_t)N_NODES * DH2];    // x @ W12
__device__ float g_Z [(size_t)N_NODES * DH2];    // spmm(Y) + c1
__device__ float g_data[(size_t)N_NODES * DH2];  // row-normalized embeds
__device__ int   g_rowptr[N_NODES + 1];
__device__ int   g_wptr  [N_NODES + 1];
__device__ int2  g_srcw[N_EDGES];                // (src, w-bits) grouped by dst
__device__ float g_mu[KCLUST * DH2];
__device__ float g_cmean[KCLUST * DH2];
__device__ float g_cr[KCLUST];

// ---------------- small utility kernels ----------------
__global__ void zero_int_k(int* p, int n) {
    int t = blockIdx.x * blockDim.x + threadIdx.x;
    if (t < n) p[t] = 0;
}
__global__ void copy_int_k(const int* s, int* d, int n) {
    int t = blockIdx.x * blockDim.x + threadIdx.x;
    if (t < n) d[t] = s[t];
}
__global__ void copy_f_k(const float* s, float* d, int n) {
    int t = blockIdx.x * blockDim.x + threadIdx.x;
    if (t < n) d[t] = s[t];
}
__global__ void zero_accum_k() {
    int t = blockIdx.x * blockDim.x + threadIdx.x;
    if (t < KCLUST * DH2) g_cmean[t] = 0.0f;
    if (t < KCLUST) g_cr[t] = 0.0f;
}
__global__ void mu_update_k() {
    int t = blockIdx.x * blockDim.x + threadIdx.x;
    if (t < KCLUST * DH2) g_mu[t] = g_cmean[t] / g_cr[t >> 8];
}
// c1 = b1 @ W2 : one block of 256 threads
__global__ void gemv_c1_k(const float* __restrict__ b1, const float* __restrict__ W2) {
    int j = threadIdx.x;
    float s = 0.0f;
    #pragma unroll 4
    for (int i = 0; i < DH1; i++) s += b1[i] * W2[i * DH2 + j];
    g_c1[j] = s;
}

// ---------------- CSR build ----------------
__global__ void hist_k(const int* __restrict__ dst, int* __restrict__ counts, int E) {
    int e = blockIdx.x * blockDim.x + threadIdx.x;
    if (e < E) atomicAdd(&counts[dst[e]], 1);
}

__global__ void scan_block_k(const int* __restrict__ counts, int* __restrict__ rowptr, int n) {
    __shared__ int ssum[1024];
    int tid = threadIdx.x;
    int chunk = (n + 1023) >> 10;
    int beg = tid * chunk;
    int end = min(beg + chunk, n);
    int s = 0;
    for (int i = beg; i < end; i++) s += counts[i];
    ssum[tid] = s;
    __syncthreads();
    for (int off = 1; off < 1024; off <<= 1) {
        int v = (tid >= off) ? ssum[tid - off] : 0;
        __syncthreads();
        ssum[tid] += v;
        __syncthreads();
    }
    int run = (tid > 0) ? ssum[tid - 1] : 0;
    for (int i = beg; i < end; i++) { rowptr[i] = run; run += counts[i]; }
    if (tid == 0) rowptr[n] = ssum[1023];
}

__global__ void scatter_k(const int* __restrict__ src, const int* __restrict__ dst,
                          const float* __restrict__ w, int* __restrict__ wptr,
                          int2* __restrict__ srcw, int E) {
    int e = blockIdx.x * blockDim.x + threadIdx.x;
    if (e < E) {
        int p = atomicAdd(&wptr[dst[e]], 1);
        srcw[p] = make_int2(src[e], __float_as_int(w[e]));
    }
}

// ---------------- SpMM via CSR: out[d] = sum_e w_e * Yin[src_e] + bias ----------------
// D=256, 64 threads/block, one dst row per block.
// FUSE_NORM: also write normOut = (acc+bias)/||acc+bias|| (fused row-normalize).
template <bool FUSE_NORM>
__global__ void spmm256_k(const float* __restrict__ Yin, float* __restrict__ out,
                          const float* __restrict__ bias, float* __restrict__ normOut) {
    constexpr int D = 256;
    constexpr int T = 64;
    __shared__ int2 meta[T];
    __shared__ float swsum[2];
    int d = blockIdx.x;
    int tid = threadIdx.x;
    int s0 = g_rowptr[d], s1 = g_rowptr[d + 1];
    float4 acc = make_float4(0.f, 0.f, 0.f, 0.f);
    for (int base = s0; base < s1; base += T) {
        int cnt = min(T, s1 - base);
        __syncthreads();
        if (tid < cnt) meta[tid] = g_srcw[base + tid];
        __syncthreads();
        int i = 0;
        for (; i + 4 <= cnt; i += 4) {
            int2 m0 = meta[i], m1 = meta[i + 1], m2 = meta[i + 2], m3 = meta[i + 3];
            float4 v0 = *(const float4*)(Yin + (size_t)m0.x * D + tid * 4);
            float4 v1 = *(const float4*)(Yin + (size_t)m1.x * D + tid * 4);
            float4 v2 = *(const float4*)(Yin + (size_t)m2.x * D + tid * 4);
            float4 v3 = *(const float4*)(Yin + (size_t)m3.x * D + tid * 4);
            float w0 = __int_as_float(m0.y), w1 = __int_as_float(m1.y);
            float w2 = __int_as_float(m2.y), w3 = __int_as_float(m3.y);
            acc.x += w0 * v0.x; acc.y += w0 * v0.y; acc.z += w0 * v0.z; acc.w += w0 * v0.w;
            acc.x += w1 * v1.x; acc.y += w1 * v1.y; acc.z += w1 * v1.z; acc.w += w1 * v1.w;
            acc.x += w2 * v2.x; acc.y += w2 * v2.y; acc.z += w2 * v2.z; acc.w += w2 * v2.w;
            acc.x += w3 * v3.x; acc.y += w3 * v3.y; acc.z += w3 * v3.z; acc.w += w3 * v3.w;
        }
        for (; i < cnt; i++) {
            int2 m = meta[i];
            float4 v = *(const float4*)(Yin + (size_t)m.x * D + tid * 4);
            float w = __int_as_float(m.y);
            acc.x += w * v.x; acc.y += w * v.y; acc.z += w * v.z; acc.w += w * v.w;
        }
    }
    float4 b = *(const float4*)(bias + tid * 4);
    acc.x += b.x; acc.y += b.y; acc.z += b.z; acc.w += b.w;
    *(float4*)(out + (size_t)d * D + tid * 4) = acc;
    if (FUSE_NORM) {
        float s = acc.x * acc.x + acc.y * acc.y + acc.z * acc.z + acc.w * acc.w;
        #pragma unroll
        for (int o = 16; o > 0; o >>= 1) s += __shfl_xor_sync(0xffffffffu, s, o);
        if ((tid & 31) == 0) swsum[tid >> 5] = s;
        __syncthreads();
        float inv = rsqrtf(swsum[0] + swsum[1]);
        acc.x *= inv; acc.y *= inv; acc.z *= inv; acc.w *= inv;
        *(float4*)(normOut + (size_t)d * D + tid * 4) = acc;
    }
}

// ---------------- SGEMM: C[M,N] = A[M,K] @ B[K,N], row-major, fp32 ----------------
// 128x128 tile, BK=16, 256 threads, 8x8 micro (f32x2), double-buffered + reg prefetch
__global__ __launch_bounds__(256) void sgemm128_k(const float* __restrict__ A,
                                                  const float* __restrict__ B,
                                                  float* __restrict__ C,
                                                  int M, int N, int K) {
    __shared__ float As[2][16][132];
    __shared__ float Bs[2][16][128];
    int tid = threadIdx.x;
    int m0 = (tid & 15) * 8;
    int n0 = (tid >> 4) * 8;
    int blockM = blockIdx.x * 128;
    int blockN = blockIdx.y * 128;

    int aM[2], aKq[2], bKr[2], bNq[2];
    bool aOk[2];
    #pragma unroll
    for (int l = 0; l < 2; l++) {
        int lin = tid + l * 256;
        aM[l] = lin >> 2;
        aKq[l] = (lin & 3) * 4;
        aOk[l] = (blockM + aM[l]) < M;
        bKr[l] = lin >> 5;
        bNq[l] = (lin & 31) * 4;
    }

    unsigned long long accp[8][4];
    #pragma unroll
    for (int i = 0; i < 8; i++)
        #pragma unroll
        for (int j = 0; j < 4; j++) accp[i][j] = 0ull;

    const int KT = K >> 4;
    {
        #pragma unroll
        for (int l = 0; l < 2; l++) {
            float4 v = make_float4(0.f, 0.f, 0.f, 0.f);
            if (aOk[l]) v = *(const float4*)(A + (size_t)(blockM + aM[l]) * K + aKq[l]);
            As[0][aKq[l] + 0][aM[l]] = v.x; As[0][aKq[l] + 1][aM[l]] = v.y;
            As[0][aKq[l] + 2][aM[l]] = v.z; As[0][aKq[l] + 3][aM[l]] = v.w;
            float4 u = *(const float4*)(B + (size_t)bKr[l] * N + blockN + bNq[l]);
            *(float4*)&Bs[0][bKr[l]][bNq[l]] = u;
        }
    }
    __syncthreads();

    for (int kt = 0; kt < KT; kt++) {
        int buf = kt & 1;
        float4 pa[2], pb[2];
        bool more = (kt + 1) < KT;
        if (more) {
            int k0 = (kt + 1) << 4;
            #pragma unroll
            for (int l = 0; l < 2; l++) {
                pa[l] = make_float4(0.f, 0.f, 0.f, 0.f);
                if (aOk[l]) pa[l] = *(const float4*)(A + (size_t)(blockM + aM[l]) * K + k0 + aKq[l]);
                pb[l] = *(const float4*)(B + (size_t)(k0 + bKr[l]) * N + blockN + bNq[l]);
            }
        }
        #pragma unroll
        for (int k = 0; k < 16; k++) {
            float4 a0 = *(const float4*)&As[buf][k][m0];
            float4 a1 = *(const float4*)&As[buf][k][m0 + 4];
            float4 b0 = *(const float4*)&Bs[buf][k][n0];
            float4 b1 = *(const float4*)&Bs[buf][k][n0 + 4];
            unsigned long long bp[4];
            bp[0] = pack2(b0.x, b0.y); bp[1] = pack2(b0.z, b0.w);
            bp[2] = pack2(b1.x, b1.y); bp[3] = pack2(b1.z, b1.w);
            float av[8] = {a0.x, a0.y, a0.z, a0.w, a1.x, a1.y, a1.z, a1.w};
            #pragma unroll
            for (int i = 0; i < 8; i++) {
                unsigned long long ap = pack2(av[i], av[i]);
                #pragma unroll
                for (int j = 0; j < 4; j++) accp[i][j] = fma2(ap, bp[j], accp[i][j]);
            }
        }
        if (more) {
            int nb = 1 - buf;
            #pragma unroll
            for (int l = 0; l < 2; l++) {
                As[nb][aKq[l] + 0][aM[l]] = pa[l].x; As[nb][aKq[l] + 1][aM[l]] = pa[l].y;
                As[nb][aKq[l] + 2][aM[l]] = pa[l].z; As[nb][aKq[l] + 3][aM[l]] = pa[l].w;
                *(float4*)&Bs[nb][bKr[l]][bNq[l]] = pb[l];
            }
        }
        __syncthreads();
    }

    #pragma unroll
    for (int i = 0; i < 8; i++) {
        int gm = blockM + m0 + i;
        if (gm < M) {
            float4 c0, c1;
            unpack2(accp[i][0], c0.x, c0.y); unpack2(accp[i][1], c0.z, c0.w);
            unpack2(accp[i][2], c1.x, c1.y); unpack2(accp[i][3], c1.z, c1.w);
            *(float4*)(C + (size_t)gm * N + blockN + n0) = c0;
            *(float4*)(C + (size_t)gm * N + blockN + n0 + 4) = c1;
        }
    }
}

// ---------------- FUSED k-means iteration ----------------
#define FUSED_SMEM_FLOATS (64 * 260 + 64 * 65 + 64 * 36)
__global__ __launch_bounds__(256, 2) void kmeans_fused_k(const float* __restrict__ data) {
    extern __shared__ float smemf[];
    float* sdata = smemf;                 // [64][260]
    float* sdist = sdata + 64 * 260;      // [64][65] (dist, then r in-place)
    float* smu   = sdist + 64 * 65;       // [64][36]

    int tid = threadIdx.x;
    int mr = tid & 15;
    int k0 = (tid >> 4) * 4;
    int lane = tid & 31, warp = tid >> 5;

    unsigned long long accB[4][8];
    #pragma unroll
    for (int i = 0; i < 4; i++)
        #pragma unroll
        for (int c = 0; c < 8; c++) accB[i][c] = 0ull;
    float accR[4] = {0.f, 0.f, 0.f, 0.f};

    const int nTiles = (N_NODES + 63) >> 6;
    for (int t = blockIdx.x; t < nTiles; t += gridDim.x) {
        int tileBase = t << 6;
        __syncthreads();

        #pragma unroll
        for (int l = 0; l < 16; l++) {
            int lin = tid + l * 256;
            int row = lin >> 6;
            int q = (lin & 63) * 4;
            int gr = tileBase + row;
            float4 v = make_float4(0.f, 0.f, 0.f, 0.f);
            if (gr < N_NODES) v = *(const float4*)(data + (size_t)gr * DH2 + q);
            *(float4*)&sdata[row * 260 + q] = v;
        }

        unsigned long long accA[4][2];
        #pragma unroll
        for (int i = 0; i < 4; i++) { accA[i][0] = 0ull; accA[i][1] = 0ull; }

        for (int kk = 0; kk < DH2; kk += 32) {
            __syncthreads();
            #pragma unroll
            for (int l = 0; l < 2; l++) {
                int lin = tid + l * 256;
                int row = lin >> 3;
                int q = (lin & 7) * 4;
                *(float4*)&smu[row * 36 + q] = *(const float4*)(g_mu + row * DH2 + kk + q);
            }
            __syncthreads();
            #pragma unroll
            for (int j = 0; j < 32; j += 4) {
                float4 a4[4], b4[4];
                #pragma unroll
                for (int i = 0; i < 4; i++) a4[i] = *(const float4*)&sdata[(mr + 16 * i) * 260 + kk + j];
                #pragma unroll
                for (int c = 0; c < 4; c++) b4[c] = *(const float4*)&smu[(k0 + c) * 36 + j];
                const float* af = (const float*)a4;
                const float* bf = (const float*)b4;
                #pragma unroll
                for (int jj = 0; jj < 4; jj++) {
                    unsigned long long bp0 = pack2(bf[0 * 4 + jj], bf[1 * 4 + jj]);
                    unsigned long long bp1 = pack2(bf[2 * 4 + jj], bf[3 * 4 + jj]);
                    #pragma unroll
                    for (int i = 0; i < 4; i++) {
                        float a = af[i * 4 + jj];
                        unsigned long long ap = pack2(a, a);
                        accA[i][0] = fma2(ap, bp0, accA[i][0]);
                        accA[i][1] = fma2(ap, bp1, accA[i][1]);
                    }
                }
            }
        }
        #pragma unroll
        for (int i = 0; i < 4; i++) {
            float c0, c1, c2, c3;
            unpack2(accA[i][0], c0, c1);
            unpack2(accA[i][1], c2, c3);
            float* dp = &sdist[(mr + 16 * i) * 65 + k0];
            dp[0] = c0; dp[1] = c1; dp[2] = c2; dp[3] = c3;
        }
        __syncthreads();

        for (int rr = warp; rr < 64; rr += 8) {
            float v0 = sdist[rr * 65 + lane];
            float v1 = sdist[rr * 65 + 32 + lane];
            float mx = fmaxf(v0, v1);
            #pragma unroll
            for (int o = 16; o > 0; o >>= 1) mx = fmaxf(mx, __shfl_xor_sync(0xffffffffu, mx, o));
            float e0 = expf(30.0f * (v0 - mx));
            float e1 = expf(30.0f * (v1 - mx));
            float s = e0 + e1;
            #pragma unroll
            for (int o = 16; o > 0; o >>= 1) s += __shfl_xor_sync(0xffffffffu, s, o);
            float inv = 1.0f / s;
            bool ok = (tileBase + rr) < N_NODES;
            sdist[rr * 65 + lane] = ok ? e0 * inv : 0.0f;
            sdist[rr * 65 + 32 + lane] = ok ? e1 * inv : 0.0f;
        }
        __syncthreads();

        #pragma unroll 4
        for (int rit = 0; rit < 64; rit++) {
            int row = (rit + k0) & 63;
            float rv[4];
            unsigned long long rvp[4];
            #pragma unroll
            for (int i = 0; i < 4; i++) {
                rv[i] = sdist[row * 65 + k0 + i];
                rvp[i] = pack2(rv[i], rv[i]);
            }
            #pragma unroll
            for (int cb = 0; cb < 4; cb++) {
                float4 dv = *(const float4*)&sdata[row * 260 + mr * 4 + 64 * cb];
                unsigned long long dp0 = pack2(dv.x, dv.y);
                unsigned long long dp1 = pack2(dv.z, dv.w);
                #pragma unroll
                for (int i = 0; i < 4; i++) {
                    accB[i][cb * 2 + 0] = fma2(rvp[i], dp0, accB[i][cb * 2 + 0]);
                    accB[i][cb * 2 + 1] = fma2(rvp[i], dp1, accB[i][cb * 2 + 1]);
                }
            }
            if (mr == 0) {
                #pragma unroll
                for (int i = 0; i < 4; i++) accR[i] += rv[i];
            }
        }
    }

    #pragma unroll
    for (int i = 0; i < 4; i++)
        #pragma unroll
        for (int cb = 0; cb < 4; cb++) {
            int bd = mr * 4 + 64 * cb;
            float lo, hi;
            unpack2(accB[i][cb * 2 + 0], lo, hi);
            atomicAdd(&g_cmean[(k0 + i) * DH2 + bd + 0], lo);
            atomicAdd(&g_cmean[(k0 + i) * DH2 + bd + 1], hi);
            unpack2(accB[i][cb * 2 + 1], lo, hi);
            atomicAdd(&g_cmean[(k0 + i) * DH2 + bd + 2], lo);
            atomicAdd(&g_cmean[(k0 + i) * DH2 + bd + 3], hi);
        }
    if (mr == 0) {
        #pragma unroll
        for (int i = 0; i < 4; i++) atomicAdd(&g_cr[k0 + i], accR[i]);
    }
}

// ---------------- final assign: writes r and dist to output ----------------
__global__ __launch_bounds__(256) void kmeans_assign_k(const float* __restrict__ data,
                                                       float* __restrict__ r_out,
                                                       float* __restrict__ dist_out) {
    __shared__ float sdata[64 * 36];
    __shared__ float smu[64 * 36];
    __shared__ float sdist[64 * 65];
    int tid = threadIdx.x;
    int rowBase = blockIdx.x * 64;
    int m0 = (tid & 15) * 4;
    int k0 = (tid >> 4) * 4;
    unsigned long long accp[4][2];
    #pragma unroll
    for (int i = 0; i < 4; i++) { accp[i][0] = 0ull; accp[i][1] = 0ull; }

    for (int kk = 0; kk < DH2; kk += 32) {
        #pragma unroll
        for (int l = 0; l < 2; l++) {
            int lin = tid + l * 256;
            int row = lin >> 3;
            int q = (lin & 7) * 4;
            int gr = rowBase + row;
            float4 v = make_float4(0.f, 0.f, 0.f, 0.f);
            if (gr < N_NODES) v = *(const float4*)(data + (size_t)gr * DH2 + kk + q);
            *(float4*)&sdata[row * 36 + q] = v;
            float4 u = *(const float4*)(g_mu + row * DH2 + kk + q);
            *(float4*)&smu[row * 36 + q] = u;
        }
        __syncthreads();
        #pragma unroll
        for (int j = 0; j < 32; j += 4) {
            float4 a4[4], b4[4];
            #pragma unroll
            for (int i = 0; i < 4; i++) a4[i] = *(const float4*)&sdata[(m0 + i) * 36 + j];
            #pragma unroll
            for (int c = 0; c < 4; c++) b4[c] = *(const float4*)&smu[(k0 + c) * 36 + j];
            const float* af = (const float*)a4;
            const float* bf = (const float*)b4;
            #pragma unroll
            for (int jj = 0; jj < 4; jj++) {
                unsigned long long bp0 = pack2(bf[0 * 4 + jj], bf[1 * 4 + jj]);
                unsigned long long bp1 = pack2(bf[2 * 4 + jj], bf[3 * 4 + jj]);
                #pragma unroll
                for (int i = 0; i < 4; i++) {
                    float a = af[i * 4 + jj];
                    unsigned long long ap = pack2(a, a);
                    accp[i][0] = fma2(ap, bp0, accp[i][0]);
                    accp[i][1] = fma2(ap, bp1, accp[i][1]);
                }
            }
        }
        __syncthreads();
    }
    #pragma unroll
    for (int i = 0; i < 4; i++) {
        float c0, c1, c2, c3;
        unpack2(accp[i][0], c0, c1);
        unpack2(accp[i][1], c2, c3);
        float* dp = &sdist[(m0 + i) * 65 + k0];
        dp[0] = c0; dp[1] = c1; dp[2] = c2; dp[3] = c3;
    }
    __syncthreads();

    int lane = tid & 31, warp = tid >> 5;
    for (int rr = warp; rr < 64; rr += 8) {
        float v0 = sdist[rr * 65 + lane];
        float v1 = sdist[rr * 65 + 32 + lane];
        float mx = fmaxf(v0, v1);
        #pragma unroll
        for (int o = 16; o > 0; o >>= 1) mx = fmaxf(mx, __shfl_xor_sync(0xffffffffu, mx, o));
        float e0 = expf(30.0f * (v0 - mx));
        float e1 = expf(30.0f * (v1 - mx));
        float s = e0 + e1;
        #pragma unroll
        for (int o = 16; o > 0; o >>= 1) s += __shfl_xor_sync(0xffffffffu, s, o);
        float inv = 1.0f / s;
        int gr = rowBase + rr;
        if (gr < N_NODES) {
            r_out[(size_t)gr * KCLUST + lane] = e0 * inv;
            r_out[(size_t)gr * KCLUST + 32 + lane] = e1 * inv;
            dist_out[(size_t)gr * KCLUST + lane] = v0;
            dist_out[(size_t)gr * KCLUST + 32 + lane] = v1;
        }
    }
}

// ---------------- host ----------------
extern "C" void kernel_launch(void* const* d_in, const int* in_sizes, int n_in,
                              void* d_out, int out_size) {
    const float* x    = (const float*)d_in[0];
    const int*   esrc = (const int*)d_in[1];
    const int*   edst = (const int*)d_in[2];
    const float* ew   = (const float*)d_in[3];
    const float* W1   = (const float*)d_in[4];
    const float* b1   = (const float*)d_in[5];
    const float* W2   = (const float*)d_in[6];
    const float* b2   = (const float*)d_in[7];
    const float* mu0  = (const float*)d_in[8];
    (void)in_sizes; (void)n_in; (void)out_size;

    float* out      = (float*)d_out;
    float* out_mu   = out;                                   // [64,256]
    float* out_r    = out_mu + KCLUST * DH2;                 // [N,64]
    float* out_emb  = out_r + (size_t)N_NODES * KCLUST;      // [N,256]
    float* out_dist = out_emb + (size_t)N_NODES * DH2;       // [N,64]

    float *pW12, *pc1, *pY, *pZ, *pdata, *pmu;
    int *prow, *pwp; int2* psrcw;
    cudaGetSymbolAddress((void**)&pW12, g_W12);
    cudaGetSymbolAddress((void**)&pc1, g_c1);
    cudaGetSymbolAddress((void**)&pY, g_Y);
    cudaGetSymbolAddress((void**)&pZ, g_Z);
    cudaGetSymbolAddress((void**)&pdata, g_data);
    cudaGetSymbolAddress((void**)&pmu, g_mu);
    cudaGetSymbolAddress((void**)&prow, g_rowptr);
    cudaGetSymbolAddress((void**)&pwp, g_wptr);
    cudaGetSymbolAddress((void**)&psrcw, g_srcw);

    static const int FUSED_SMEM_BYTES = FUSED_SMEM_FLOATS * 4;
    cudaFuncSetAttribute(kmeans_fused_k, cudaFuncAttributeMaxDynamicSharedMemorySize,
                         FUSED_SMEM_BYTES);

    // --- CSR build (by dst) ---
    zero_int_k<<<(N_NODES + 255) / 256, 256>>>(pwp, N_NODES);
    hist_k<<<(N_EDGES + 255) / 256, 256>>>(edst, pwp, N_EDGES);
    scan_block_k<<<1, 1024>>>(pwp, prow, N_NODES);
    copy_int_k<<<(N_NODES + 255) / 256, 256>>>(prow, pwp, N_NODES);
    scatter_k<<<(N_EDGES + 255) / 256, 256>>>(esrc, edst, ew, pwp, psrcw, N_EDGES);

    // --- collapsed weights: W12 = W1@W2 (512x256), c1 = b1@W2 ---
    sgemm128_k<<<dim3(DH1 / 128, DH2 / 128), 256>>>(W1, W2, pW12, DH1, DH2, DH1);
    gemv_c1_k<<<1, DH2>>>(b1, W2);

    // --- GCN forward (algebraically collapsed):
    //     embeds = A @ (A @ (x@W12) + c1) + b2
    sgemm128_k<<<dim3((N_NODES + 127) / 128, DH2 / 128), 256>>>(x, pW12, pY, N_NODES, DH2, DH1);
    spmm256_k<false><<<N_NODES, 64>>>(pY, pZ, pc1, nullptr);
    spmm256_k<true><<<N_NODES, 64>>>(pZ, out_emb, b2, pdata);   // fused normalize

    // --- k-means ---
    copy_f_k<<<(KCLUST * DH2 + 255) / 256, 256>>>(mu0, pmu, KCLUST * DH2);
    for (int it = 0; it < NUM_ITER; it++) {
        zero_accum_k<<<(KCLUST * DH2 + 255) / 256, 256>>>();
        kmeans_fused_k<<<296, 256, FUSED_SMEM_BYTES>>>(pdata);
        mu_update_k<<<(KCLUST * DH2 + 255) / 256, 256>>>();
    }
    kmeans_assign_k<<<(N_NODES + 63) / 64, 256>>>(pdata, out_r, out_dist);
    copy_f_k<<<(KCLUST * DH2 + 255) / 256, 256>>>(pmu, out_mu, KCLUST * DH2);
}

// round 15
// speedup vs baseline: 1.5476x; 1.0651x over previous
#include <cuda_runtime.h>
#include <math.h>

#define N_NODES 100000
#define N_EDGES 3200000
#define DH1 512
#define DH2 256
#define KCLUST 64
#define NUM_ITER 10
#define KMEANS_GRID 304   // 2 CTAs x 152 SMs (GB300)

// ---------------- f32x2 packed helpers (Blackwell sm_100+) ----------------
__device__ __forceinline__ unsigned long long pack2(float lo, float hi) {
    unsigned long long r;
    asm("mov.b64 %0, {%1, %2};" : "=l"(r) : "f"(lo), "f"(hi));
    return r;
}
__device__ __forceinline__ void unpack2(unsigned long long v, float& lo, float& hi) {
    asm("mov.b64 {%0, %1}, %2;" : "=f"(lo), "=f"(hi) : "l"(v));
}
__device__ __forceinline__ unsigned long long fma2(unsigned long long a,
                                                   unsigned long long b,
                                                   unsigned long long c) {
    unsigned long long d;
    asm("fma.rn.f32x2 %0, %1, %2, %3;" : "=l"(d) : "l"(a), "l"(b), "l"(c));
    return d;
}

// ---------------- scratch (device globals; no allocation allowed) ----------------
__device__ float g_W12[DH1 * DH2];               // W1 @ W2
__device__ float g_c1[DH2];                      // b1 @ W2
__device__ float g_Y [(size_t)N_NODES * DH2];    // x @ W12
__device__ float g_Z [(size_t)N_NODES * DH2];    // spmm(Y) + c1
__device__ float g_data[(size_t)N_NODES * DH2];  // row-normalized embeds
__device__ int   g_rowptr[N_NODES + 1];
__device__ int   g_wptr  [N_NODES + 1];
__device__ int2  g_srcw[N_EDGES];                // (src, w-bits) grouped by dst
__device__ float g_mu[KCLUST * DH2];
__device__ float g_cmean[KCLUST * DH2];
__device__ float g_cr[KCLUST];

// ---------------- small utility kernels ----------------
__global__ void zero_int_k(int* p, int n) {
    int t = blockIdx.x * blockDim.x + threadIdx.x;
    if (t < n) p[t] = 0;
}
__global__ void copy_f_k(const float* s, float* d, int n) {
    int t = blockIdx.x * blockDim.x + threadIdx.x;
    if (t < n) d[t] = s[t];
}
__global__ void zero_accum_k() {
    int t = blockIdx.x * blockDim.x + threadIdx.x;
    if (t < KCLUST * DH2) g_cmean[t] = 0.0f;
    if (t < KCLUST) g_cr[t] = 0.0f;
}
// one block per cluster k: mu[k,:] = cmean[k,:]/cr[k], then zero accumulators
__global__ void mu_update_zero_k() {
    __shared__ float sinv;
    int k = blockIdx.x, j = threadIdx.x;
    if (j == 0) sinv = 1.0f / g_cr[k];
    __syncthreads();
    int idx = k * DH2 + j;
    g_mu[idx] = g_cmean[idx] * sinv;
    g_cmean[idx] = 0.0f;
    __syncthreads();
    if (j == 0) g_cr[k] = 0.0f;
}
// c1 = b1 @ W2 : one block of 256 threads
__global__ void gemv_c1_k(const float* __restrict__ b1, const float* __restrict__ W2) {
    int j = threadIdx.x;
    float s = 0.0f;
    #pragma unroll 4
    for (int i = 0; i < DH1; i++) s += b1[i] * W2[i * DH2 + j];
    g_c1[j] = s;
}

// ---------------- CSR build ----------------
__global__ void hist_k(const int* __restrict__ dst, int* __restrict__ counts, int E) {
    int e = blockIdx.x * blockDim.x + threadIdx.x;
    if (e < E) atomicAdd(&counts[dst[e]], 1);
}

// exclusive scan: counts (=wptr) -> rowptr[0..n] AND wptr[i]=rowptr[i]
__global__ void scan_block_k(int* __restrict__ counts, int* __restrict__ rowptr, int n) {
    __shared__ int ssum[1024];
    int tid = threadIdx.x;
    int chunk = (n + 1023) >> 10;
    int beg = tid * chunk;
    int end = min(beg + chunk, n);
    int s = 0;
    for (int i = beg; i < end; i++) s += counts[i];
    ssum[tid] = s;
    __syncthreads();
    for (int off = 1; off < 1024; off <<= 1) {
        int v = (tid >= off) ? ssum[tid - off] : 0;
        __syncthreads();
        ssum[tid] += v;
        __syncthreads();
    }
    int run = (tid > 0) ? ssum[tid - 1] : 0;
    for (int i = beg; i < end; i++) {
        int c = counts[i];
        rowptr[i] = run;
        counts[i] = run;   // wptr = start offsets for scatter
        run += c;
    }
    if (tid == 0) rowptr[n] = ssum[1023];
}

__global__ void scatter_k(const int* __restrict__ src, const int* __restrict__ dst,
                          const float* __restrict__ w, int* __restrict__ wptr,
                          int2* __restrict__ srcw, int E) {
    int e = blockIdx.x * blockDim.x + threadIdx.x;
    if (e < E) {
        int p = atomicAdd(&wptr[dst[e]], 1);
        srcw[p] = make_int2(src[e], __float_as_int(w[e]));
    }
}

// ---------------- SpMM via CSR: out[d] = sum_e w_e * Yin[src_e] + bias ----------------
// 8-deep gather unroll for MLP=8 (L2-latency hiding).
template <bool FUSE_NORM>
__global__ void spmm256_k(const float* __restrict__ Yin, float* __restrict__ out,
                          const float* __restrict__ bias, float* __restrict__ normOut) {
    constexpr int D = 256;
    constexpr int T = 64;
    __shared__ int2 meta[T];
    __shared__ float swsum[2];
    int d = blockIdx.x;
    int tid = threadIdx.x;
    int s0 = g_rowptr[d], s1 = g_rowptr[d + 1];
    float4 acc = make_float4(0.f, 0.f, 0.f, 0.f);
    for (int base = s0; base < s1; base += T) {
        int cnt = min(T, s1 - base);
        __syncthreads();
        if (tid < cnt) meta[tid] = g_srcw[base + tid];
        __syncthreads();
        int i = 0;
        for (; i + 8 <= cnt; i += 8) {
            float4 v[8];
            float wv[8];
            #pragma unroll
            for (int u = 0; u < 8; u++) {
                int2 m = meta[i + u];
                v[u] = *(const float4*)(Yin + (size_t)m.x * D + tid * 4);
                wv[u] = __int_as_float(m.y);
            }
            #pragma unroll
            for (int u = 0; u < 8; u++) {
                acc.x += wv[u] * v[u].x; acc.y += wv[u] * v[u].y;
                acc.z += wv[u] * v[u].z; acc.w += wv[u] * v[u].w;
            }
        }
        for (; i + 4 <= cnt; i += 4) {
            float4 v[4];
            float wv[4];
            #pragma unroll
            for (int u = 0; u < 4; u++) {
                int2 m = meta[i + u];
                v[u] = *(const float4*)(Yin + (size_t)m.x * D + tid * 4);
                wv[u] = __int_as_float(m.y);
            }
            #pragma unroll
            for (int u = 0; u < 4; u++) {
                acc.x += wv[u] * v[u].x; acc.y += wv[u] * v[u].y;
                acc.z += wv[u] * v[u].z; acc.w += wv[u] * v[u].w;
            }
        }
        for (; i < cnt; i++) {
            int2 m = meta[i];
            float4 v = *(const float4*)(Yin + (size_t)m.x * D + tid * 4);
            float w = __int_as_float(m.y);
            acc.x += w * v.x; acc.y += w * v.y; acc.z += w * v.z; acc.w += w * v.w;
        }
    }
    float4 b = *(const float4*)(bias + tid * 4);
    acc.x += b.x; acc.y += b.y; acc.z += b.z; acc.w += b.w;
    *(float4*)(out + (size_t)d * D + tid * 4) = acc;
    if (FUSE_NORM) {
        float s = acc.x * acc.x + acc.y * acc.y + acc.z * acc.z + acc.w * acc.w;
        #pragma unroll
        for (int o = 16; o > 0; o >>= 1) s += __shfl_xor_sync(0xffffffffu, s, o);
        if ((tid & 31) == 0) swsum[tid >> 5] = s;
        __syncthreads();
        float inv = rsqrtf(swsum[0] + swsum[1]);
        acc.x *= inv; acc.y *= inv; acc.z *= inv; acc.w *= inv;
        *(float4*)(normOut + (size_t)d * D + tid * 4) = acc;
    }
}

// ---------------- SGEMM: C[M,N] = A[M,K] @ B[K,N], row-major, fp32 ----------------
// b-operand pairs loaded directly as u64 from smem (no pack2 on b-side).
__global__ __launch_bounds__(256) void sgemm128_k(const float* __restrict__ A,
                                                  const float* __restrict__ B,
                                                  float* __restrict__ C,
                                                  int M, int N, int K) {
    __shared__ float As[2][16][132];
    __shared__ float Bs[2][16][128];
    int tid = threadIdx.x;
    int m0 = (tid & 15) * 8;
    int n0 = (tid >> 4) * 8;
    int blockM = blockIdx.x * 128;
    int blockN = blockIdx.y * 128;

    int aM[2], aKq[2], bKr[2], bNq[2];
    bool aOk[2];
    #pragma unroll
    for (int l = 0; l < 2; l++) {
        int lin = tid + l * 256;
        aM[l] = lin >> 2;
        aKq[l] = (lin & 3) * 4;
        aOk[l] = (blockM + aM[l]) < M;
        bKr[l] = lin >> 5;
        bNq[l] = (lin & 31) * 4;
    }

    unsigned long long accp[8][4];
    #pragma unroll
    for (int i = 0; i < 8; i++)
        #pragma unroll
        for (int j = 0; j < 4; j++) accp[i][j] = 0ull;

    const int KT = K >> 4;
    {
        #pragma unroll
        for (int l = 0; l < 2; l++) {
            float4 v = make_float4(0.f, 0.f, 0.f, 0.f);
            if (aOk[l]) v = *(const float4*)(A + (size_t)(blockM + aM[l]) * K + aKq[l]);
            As[0][aKq[l] + 0][aM[l]] = v.x; As[0][aKq[l] + 1][aM[l]] = v.y;
            As[0][aKq[l] + 2][aM[l]] = v.z; As[0][aKq[l] + 3][aM[l]] = v.w;
            float4 u = *(const float4*)(B + (size_t)bKr[l] * N + blockN + bNq[l]);
            *(float4*)&Bs[0][bKr[l]][bNq[l]] = u;
        }
    }
    __syncthreads();

    for (int kt = 0; kt < KT; kt++) {
        int buf = kt & 1;
        float4 pa[2], pb[2];
        bool more = (kt + 1) < KT;
        if (more) {
            int k0 = (kt + 1) << 4;
            #pragma unroll
            for (int l = 0; l < 2; l++) {
                pa[l] = make_float4(0.f, 0.f, 0.f, 0.f);
                if (aOk[l]) pa[l] = *(const float4*)(A + (size_t)(blockM + aM[l]) * K + k0 + aKq[l]);
                pb[l] = *(const float4*)(B + (size_t)(k0 + bKr[l]) * N + blockN + bNq[l]);
            }
        }
        #pragma unroll
        for (int k = 0; k < 16; k++) {
            float4 a0 = *(const float4*)&As[buf][k][m0];
            float4 a1 = *(const float4*)&As[buf][k][m0 + 4];
            const unsigned long long* bq = (const unsigned long long*)&Bs[buf][k][n0];
            unsigned long long bp0 = bq[0], bp1 = bq[1], bp2 = bq[2], bp3 = bq[3];
            float av[8] = {a0.x, a0.y, a0.z, a0.w, a1.x, a1.y, a1.z, a1.w};
            #pragma unroll
            for (int i = 0; i < 8; i++) {
                unsigned long long ap = pack2(av[i], av[i]);
                accp[i][0] = fma2(ap, bp0, accp[i][0]);
                accp[i][1] = fma2(ap, bp1, accp[i][1]);
                accp[i][2] = fma2(ap, bp2, accp[i][2]);
                accp[i][3] = fma2(ap, bp3, accp[i][3]);
            }
        }
        if (more) {
            int nb = 1 - buf;
            #pragma unroll
            for (int l = 0; l < 2; l++) {
                As[nb][aKq[l] + 0][aM[l]] = pa[l].x; As[nb][aKq[l] + 1][aM[l]] = pa[l].y;
                As[nb][aKq[l] + 2][aM[l]] = pa[l].z; As[nb][aKq[l] + 3][aM[l]] = pa[l].w;
                *(float4*)&Bs[nb][bKr[l]][bNq[l]] = pb[l];
            }
        }
        __syncthreads();
    }

    #pragma unroll
    for (int i = 0; i < 8; i++) {
        int gm = blockM + m0 + i;
        if (gm < M) {
            float4 c0, c1;
            unpack2(accp[i][0], c0.x, c0.y); unpack2(accp[i][1], c0.z, c0.w);
            unpack2(accp[i][2], c1.x, c1.y); unpack2(accp[i][3], c1.z, c1.w);
            *(float4*)(C + (size_t)gm * N + blockN + n0) = c0;
            *(float4*)(C + (size_t)gm * N + blockN + n0 + 4) = c1;
        }
    }
}

// ---------------- FUSED k-means iteration ----------------
// Phase A uses j-pair packing: acc2 holds (even-j, odd-j) partial sums; no pack2
// in the inner loop, mu kept in natural [k][j] layout.
// smem: sdata[64][260] | sdist[64][65] | smu[64][36]
#define FUSED_SMEM_FLOATS (64 * 260 + 64 * 65 + 64 * 36)
__global__ __launch_bounds__(256, 2) void kmeans_fused_k(const float* __restrict__ data) {
    extern __shared__ float smemf[];
    float* sdata = smemf;                 // [64][260]
    float* sdist = sdata + 64 * 260;      // [64][65] (dist, then r in-place)
    float* smu   = sdist + 64 * 65;       // [64][36]

    int tid = threadIdx.x;
    int mr = tid & 15;
    int k0 = (tid >> 4) * 4;
    int lane = tid & 31, warp = tid >> 5;

    unsigned long long accB[4][8];
    #pragma unroll
    for (int i = 0; i < 4; i++)
        #pragma unroll
        for (int c = 0; c < 8; c++) accB[i][c] = 0ull;
    float accR[4] = {0.f, 0.f, 0.f, 0.f};

    const int nTiles = (N_NODES + 63) >> 6;
    for (int t = blockIdx.x; t < nTiles; t += gridDim.x) {
        int tileBase = t << 6;
        __syncthreads();

        #pragma unroll
        for (int l = 0; l < 16; l++) {
            int lin = tid + l * 256;
            int row = lin >> 6;
            int q = (lin & 63) * 4;
            int gr = tileBase + row;
            float4 v = make_float4(0.f, 0.f, 0.f, 0.f);
            if (gr < N_NODES) v = *(const float4*)(data + (size_t)gr * DH2 + q);
            *(float4*)&sdata[row * 260 + q] = v;
        }

        // Phase A: dist with (even,odd) packed partial sums
        unsigned long long acc2[4][4];
        #pragma unroll
        for (int i = 0; i < 4; i++)
            #pragma unroll
            for (int c = 0; c < 4; c++) acc2[i][c] = 0ull;

        for (int kk = 0; kk < DH2; kk += 32) {
            __syncthreads();
            // load mu natural layout: smu[k][j] = mu[k][kk+j], 64x32
            #pragma unroll
            for (int l = 0; l < 2; l++) {
                int lin = tid + l * 256;   // 512 float4
                int row = lin >> 3;
                int q = (lin & 7) * 4;
                *(float4*)&smu[row * 36 + q] = *(const float4*)(g_mu + row * DH2 + kk + q);
            }
            __syncthreads();
            #pragma unroll
            for (int j4 = 0; j4 < 32; j4 += 4) {
                unsigned long long a2[4][2];
                #pragma unroll
                for (int i = 0; i < 4; i++) {
                    const unsigned long long* ap =
                        (const unsigned long long*)&sdata[(mr + 16 * i) * 260 + kk + j4];
                    a2[i][0] = ap[0]; a2[i][1] = ap[1];
                }
                #pragma unroll
                for (int c = 0; c < 4; c++) {
                    const unsigned long long* bp =
                        (const unsigned long long*)&smu[(k0 + c) * 36 + j4];
                    unsigned long long b0 = bp[0], b1 = bp[1];
                    #pragma unroll
                    for (int i = 0; i < 4; i++) {
                        acc2[i][c] = fma2(a2[i][0], b0, acc2[i][c]);
                        acc2[i][c] = fma2(a2[i][1], b1, acc2[i][c]);
                    }
                }
            }
        }
        #pragma unroll
        for (int i = 0; i < 4; i++) {
            float* dp = &sdist[(mr + 16 * i) * 65 + k0];
            #pragma unroll
            for (int c = 0; c < 4; c++) {
                float lo, hi;
                unpack2(acc2[i][c], lo, hi);
                dp[c] = lo + hi;
            }
        }
        __syncthreads();

        for (int rr = warp; rr < 64; rr += 8) {
            float v0 = sdist[rr * 65 + lane];
            float v1 = sdist[rr * 65 + 32 + lane];
            float mx = fmaxf(v0, v1);
            #pragma unroll
            for (int o = 16; o > 0; o >>= 1) mx = fmaxf(mx, __shfl_xor_sync(0xffffffffu, mx, o));
            float e0 = __expf(30.0f * (v0 - mx));
            float e1 = __expf(30.0f * (v1 - mx));
            float s = e0 + e1;
            #pragma unroll
            for (int o = 16; o > 0; o >>= 1) s += __shfl_xor_sync(0xffffffffu, s, o);
            float inv = 1.0f / s;
            bool ok = (tileBase + rr) < N_NODES;
            sdist[rr * 65 + lane] = ok ? e0 * inv : 0.0f;
            sdist[rr * 65 + 32 + lane] = ok ? e1 * inv : 0.0f;
        }
        __syncthreads();

        #pragma unroll 4
        for (int rit = 0; rit < 64; rit++) {
            int row = (rit + k0) & 63;
            float rv[4];
            unsigned long long rvp[4];
            #pragma unroll
            for (int i = 0; i < 4; i++) {
                rv[i] = sdist[row * 65 + k0 + i];
                rvp[i] = pack2(rv[i], rv[i]);
            }
            #pragma unroll
            for (int cb = 0; cb < 4; cb++) {
                const unsigned long long* dpp =
                    (const unsigned long long*)&sdata[row * 260 + mr * 4 + 64 * cb];
                unsigned long long dp0 = dpp[0];
                unsigned long long dp1 = dpp[1];
                #pragma unroll
                for (int i = 0; i < 4; i++) {
                    accB[i][cb * 2 + 0] = fma2(rvp[i], dp0, accB[i][cb * 2 + 0]);
                    accB[i][cb * 2 + 1] = fma2(rvp[i], dp1, accB[i][cb * 2 + 1]);
                }
            }
            if (mr == 0) {
                #pragma unroll
                for (int i = 0; i < 4; i++) accR[i] += rv[i];
            }
        }
    }

    #pragma unroll
    for (int i = 0; i < 4; i++)
        #pragma unroll
        for (int cb = 0; cb < 4; cb++) {
            int bd = mr * 4 + 64 * cb;
            float lo, hi;
            unpack2(accB[i][cb * 2 + 0], lo, hi);
            atomicAdd(&g_cmean[(k0 + i) * DH2 + bd + 0], lo);
            atomicAdd(&g_cmean[(k0 + i) * DH2 + bd + 1], hi);
            unpack2(accB[i][cb * 2 + 1], lo, hi);
            atomicAdd(&g_cmean[(k0 + i) * DH2 + bd + 2], lo);
            atomicAdd(&g_cmean[(k0 + i) * DH2 + bd + 3], hi);
        }
    if (mr == 0) {
        #pragma unroll
        for (int i = 0; i < 4; i++) atomicAdd(&g_cr[k0 + i], accR[i]);
    }
}

// ---------------- final assign: writes r and dist to output ----------------
__global__ __launch_bounds__(256) void kmeans_assign_k(const float* __restrict__ data,
                                                       float* __restrict__ r_out,
                                                       float* __restrict__ dist_out) {
    __shared__ float sdata[64 * 36];
    __shared__ float smu[64 * 36];
    __shared__ float sdist[64 * 65];
    int tid = threadIdx.x;
    int rowBase = blockIdx.x * 64;
    int m0 = (tid & 15) * 4;
    int k0 = (tid >> 4) * 4;
    unsigned long long acc2[4][4];
    #pragma unroll
    for (int i = 0; i < 4; i++)
        #pragma unroll
        for (int c = 0; c < 4; c++) acc2[i][c] = 0ull;

    for (int kk = 0; kk < DH2; kk += 32) {
        #pragma unroll
        for (int l = 0; l < 2; l++) {
            int lin = tid + l * 256;
            int row = lin >> 3;
            int q = (lin & 7) * 4;
            int gr = rowBase + row;
            float4 v = make_float4(0.f, 0.f, 0.f, 0.f);
            if (gr < N_NODES) v = *(const float4*)(data + (size_t)gr * DH2 + kk + q);
            *(float4*)&sdata[row * 36 + q] = v;
            float4 u = *(const float4*)(g_mu + row * DH2 + kk + q);
            *(float4*)&smu[row * 36 + q] = u;
        }
        __syncthreads();
        #pragma unroll
        for (int j4 = 0; j4 < 32; j4 += 4) {
            unsigned long long a2[4][2];
            #pragma unroll
            for (int i = 0; i < 4; i++) {
                const unsigned long long* ap =
                    (const unsigned long long*)&sdata[(m0 + i) * 36 + j4];
                a2[i][0] = ap[0]; a2[i][1] = ap[1];
            }
            #pragma unroll
            for (int c = 0; c < 4; c++) {
                const unsigned long long* bp =
                    (const unsigned long long*)&smu[(k0 + c) * 36 + j4];
                unsigned long long b0 = bp[0], b1 = bp[1];
                #pragma unroll
                for (int i = 0; i < 4; i++) {
                    acc2[i][c] = fma2(a2[i][0], b0, acc2[i][c]);
                    acc2[i][c] = fma2(a2[i][1], b1, acc2[i][c]);
                }
            }
        }
        __syncthreads();
    }
    #pragma unroll
    for (int i = 0; i < 4; i++) {
        float* dp = &sdist[(m0 + i) * 65 + k0];
        #pragma unroll
        for (int c = 0; c < 4; c++) {
            float lo, hi;
            unpack2(acc2[i][c], lo, hi);
            dp[c] = lo + hi;
        }
    }
    __syncthreads();

    int lane = tid & 31, warp = tid >> 5;
    for (int rr = warp; rr < 64; rr += 8) {
        float v0 = sdist[rr * 65 + lane];
        float v1 = sdist[rr * 65 + 32 + lane];
        float mx = fmaxf(v0, v1);
        #pragma unroll
        for (int o = 16; o > 0; o >>= 1) mx = fmaxf(mx, __shfl_xor_sync(0xffffffffu, mx, o));
        float e0 = __expf(30.0f * (v0 - mx));
        float e1 = __expf(30.0f * (v1 - mx));
        float s = e0 + e1;
        #pragma unroll
        for (int o = 16; o > 0; o >>= 1) s += __shfl_xor_sync(0xffffffffu, s, o);
        float inv = 1.0f / s;
        int gr = rowBase + rr;
        if (gr < N_NODES) {
            r_out[(size_t)gr * KCLUST + lane] = e0 * inv;
            r_out[(size_t)gr * KCLUST + 32 + lane] = e1 * inv;
            dist_out[(size_t)gr * KCLUST + lane] = v0;
            dist_out[(size_t)gr * KCLUST + 32 + lane] = v1;
        }
    }
}

// ---------------- host ----------------
extern "C" void kernel_launch(void* const* d_in, const int* in_sizes, int n_in,
                              void* d_out, int out_size) {
    const float* x    = (const float*)d_in[0];
    const int*   esrc = (const int*)d_in[1];
    const int*   edst = (const int*)d_in[2];
    const float* ew   = (const float*)d_in[3];
    const float* W1   = (const float*)d_in[4];
    const float* b1   = (const float*)d_in[5];
    const float* W2   = (const float*)d_in[6];
    const float* b2   = (const float*)d_in[7];
    const float* mu0  = (const float*)d_in[8];
    (void)in_sizes; (void)n_in; (void)out_size;

    float* out      = (float*)d_out;
    float* out_mu   = out;                                   // [64,256]
    float* out_r    = out_mu + KCLUST * DH2;                 // [N,64]
    float* out_emb  = out_r + (size_t)N_NODES * KCLUST;      // [N,256]
    float* out_dist = out_emb + (size_t)N_NODES * DH2;       // [N,64]

    float *pW12, *pc1, *pY, *pZ, *pdata, *pmu;
    int *prow, *pwp; int2* psrcw;
    cudaGetSymbolAddress((void**)&pW12, g_W12);
    cudaGetSymbolAddress((void**)&pc1, g_c1);
    cudaGetSymbolAddress((void**)&pY, g_Y);
    cudaGetSymbolAddress((void**)&pZ, g_Z);
    cudaGetSymbolAddress((void**)&pdata, g_data);
    cudaGetSymbolAddress((void**)&pmu, g_mu);
    cudaGetSymbolAddress((void**)&prow, g_rowptr);
    cudaGetSymbolAddress((void**)&pwp, g_wptr);
    cudaGetSymbolAddress((void**)&psrcw, g_srcw);

    static const int FUSED_SMEM_BYTES = FUSED_SMEM_FLOATS * 4;
    cudaFuncSetAttribute(kmeans_fused_k, cudaFuncAttributeMaxDynamicSharedMemorySize,
                         FUSED_SMEM_BYTES);

    // 1: W12 = W1@W2
    sgemm128_k<<<dim3(DH1 / 128, DH2 / 128), 256>>>(W1, W2, pW12, DH1, DH2, DH1);
    // 2: c1 = b1@W2
    gemv_c1_k<<<1, DH2>>>(b1, W2);
    // 3: zero wptr
    zero_int_k<<<(N_NODES + 255) / 256, 256>>>(pwp, N_NODES);
    // 4: Y = x@W12   (ncu capture slot)
    sgemm128_k<<<dim3((N_NODES + 127) / 128, DH2 / 128), 256>>>(x, pW12, pY, N_NODES, DH2, DH1);
    // 5-7: CSR build
    hist_k<<<(N_EDGES + 255) / 256, 256>>>(edst, pwp, N_EDGES);
    scan_block_k<<<1, 1024>>>(pwp, prow, N_NODES);
    scatter_k<<<(N_EDGES + 255) / 256, 256>>>(esrc, edst, ew, pwp, psrcw, N_EDGES);
    // 8-9: two spmm passes (second fuses row-normalize)
    spmm256_k<false><<<N_NODES, 64>>>(pY, pZ, pc1, nullptr);
    spmm256_k<true><<<N_NODES, 64>>>(pZ, out_emb, b2, pdata);

    // k-means
    copy_f_k<<<(KCLUST * DH2 + 255) / 256, 256>>>(mu0, pmu, KCLUST * DH2);
    zero_accum_k<<<(KCLUST * DH2 + 255) / 256, 256>>>();
    for (int it = 0; it < NUM_ITER; it++) {
        kmeans_fused_k<<<KMEANS_GRID, 256, FUSED_SMEM_BYTES>>>(pdata);
        mu_update_zero_k<<<KCLUST, DH2>>>();
    }
    kmeans_assign_k<<<(N_NODES + 63) / 64, 256>>>(pdata, out_r, out_dist);
    copy_f_k<<<(KCLUST * DH2 + 255) / 256, 256>>>(pmu, out_mu, KCLUST * DH2);
}